// round 13
// baseline (speedup 1.0000x reference)
#include <cuda_runtime.h>
#include <cuda_bf16.h>
#include <cstdint>
#include <math.h>

#define NLAYERS 4
#define NQ      256
#define DIM     1024
#define MGAL    51200
#define KC      64
#define NCHUNK  (DIM / KC)          // 16
#define TILE_G  128
#define NTILES  (MGAL / TILE_G)     // 400
#define NCTAS   (NTILES * NLAYERS)  // 1600

#define A_SZ    (NQ * 128)          // 32768 B (256 q-rows x 128 B)
#define B_SZ    (TILE_G * 128)      // 16384 B
#define BUF     (A_SZ + B_SZ)       // 49152
#define OFF_INVN (2 * BUF)          // 98304
#define SMEM_BYTES (OFF_INVN + 512)

__device__ uint32_t g_qbf[NLAYERS * NQ * DIM / 2];  // bf16 queries (normalized), row-major
__device__ unsigned int g_simmax[NLAYERS * NQ];     // monotone-encoded max (0 == "-inf")
__device__ unsigned int g_done;                     // finished-CTA counter

// ---------------- helpers ----------------
__device__ __forceinline__ uint32_t smem_u32(const void* p) {
    uint32_t a;
    asm("{ .reg .u64 t; cvta.to.shared.u64 t, %1; cvt.u32.u64 %0, t; }" : "=r"(a) : "l"(p));
    return a;
}
#define SWZ(o) ((o) ^ (((o) >> 3) & 0x70))

__device__ __forceinline__ unsigned enc_f(float f) {
    unsigned u = __float_as_uint(f);
    return (u & 0x80000000u) ? ~u : (u | 0x80000000u);   // always > 0 for finite f > -inf
}
__device__ __forceinline__ float dec_f(unsigned u) {
    return __uint_as_float((u & 0x80000000u) ? (u & 0x7fffffffu) : ~u);
}
__device__ __forceinline__ void mma16816(float* d, const uint32_t* a, uint32_t b0, uint32_t b1) {
    asm volatile(
        "mma.sync.aligned.m16n8k16.row.col.f32.bf16.bf16.f32 "
        "{%0,%1,%2,%3}, {%4,%5,%6,%7}, {%8,%9}, {%0,%1,%2,%3};"
        : "+f"(d[0]), "+f"(d[1]), "+f"(d[2]), "+f"(d[3])
        : "r"(a[0]), "r"(a[1]), "r"(a[2]), "r"(a[3]), "r"(b0), "r"(b1));
}
__device__ __forceinline__ void ldmx4(uint32_t* r, uint32_t addr) {
    asm volatile("ldmatrix.sync.aligned.m8n8.x4.shared.b16 {%0,%1,%2,%3}, [%4];"
                 : "=r"(r[0]), "=r"(r[1]), "=r"(r[2]), "=r"(r[3]) : "r"(addr));
}

// ---------------- prep: normalize queries -> bf16 ----------------
__global__ void prep_q_kernel(const float* __restrict__ q) {
    int row = blockIdx.x;                      // l*NQ + n
    const float4 f = reinterpret_cast<const float4*>(q + (size_t)row * DIM)[threadIdx.x];
    __shared__ float red[8];
    float ss = f.x*f.x + f.y*f.y + f.z*f.z + f.w*f.w;
    #pragma unroll
    for (int o = 16; o; o >>= 1) ss += __shfl_xor_sync(~0u, ss, o);
    if ((threadIdx.x & 31) == 0) red[threadIdx.x >> 5] = ss;
    __syncthreads();
    if (threadIdx.x < 8) {
        float s = red[threadIdx.x];
        #pragma unroll
        for (int o = 4; o; o >>= 1) s += __shfl_xor_sync(0xffu, s, o);
        if (threadIdx.x == 0) red[0] = s;
    }
    __syncthreads();
    float inv = 1.0f / fmaxf(sqrtf(red[0]), 1e-8f);
    __nv_bfloat162 h0 = __floats2bfloat162_rn(f.x * inv, f.y * inv);
    __nv_bfloat162 h1 = __floats2bfloat162_rn(f.z * inv, f.w * inv);
    uint32_t* dst = g_qbf + (size_t)row * 512;
    dst[threadIdx.x * 2 + 0] = *reinterpret_cast<uint32_t*>(&h0);
    dst[threadIdx.x * 2 + 1] = *reinterpret_cast<uint32_t*>(&h1);
}

// ---------------- main bf16 GEMM + max kernel (round-2 core + fused finalize) ----------------
__global__ __launch_bounds__(256, 1)
void gemm_max_kernel(const float* __restrict__ gal, float* __restrict__ out) {
    extern __shared__ char smem[];
    const uint32_t sb = smem_u32(smem);
    const int tid = threadIdx.x, wid = tid >> 5, lid = tid & 31;
    const int l  = blockIdx.y;
    const int g0 = blockIdx.x * TILE_G;
    const float*    gB = gal + ((size_t)l * MGAL + g0) * DIM;
    const uint32_t* gA = g_qbf + (size_t)l * NQ * 512;

    const int brow = tid >> 1, bhalf = tid & 1;
    const int wm = wid >> 1, wn = wid & 1;

    float acc[4][8][4];
    #pragma unroll
    for (int mt = 0; mt < 4; mt++)
        #pragma unroll
        for (int nt = 0; nt < 8; nt++)
            #pragma unroll
            for (int e = 0; e < 4; e++) acc[mt][nt][e] = 0.0f;

    float4 pb[8];
    float ss = 0.0f;

    // prologue
    {
        const float* src = gB + (size_t)brow * DIM + bhalf * 32;
        #pragma unroll
        for (int i = 0; i < 8; i++) pb[i] = *reinterpret_cast<const float4*>(src + i * 4);
    }
    {
        const uint32_t* src = gA + (size_t)tid * 512;
        #pragma unroll
        for (int u = 0; u < 8; u++) {
            uint32_t dst = sb + SWZ((uint32_t)(tid * 128 + u * 16));
            asm volatile("cp.async.ca.shared.global [%0], [%1], 16;"
                         :: "r"(dst), "l"(src + u * 4) : "memory");
        }
        asm volatile("cp.async.commit_group;" ::: "memory");
    }

    for (int c = 0; c < NCHUNK; c++) {
        const uint32_t bufb = sb + (uint32_t)(c & 1) * BUF;
        {   // store prefetched B regs -> smem bf16 (SW128), accumulate sumsq
            #pragma unroll
            for (int i = 0; i < 8; i++) {
                float4 f = pb[i];
                ss = fmaf(f.x, f.x, fmaf(f.y, f.y, fmaf(f.z, f.z, fmaf(f.w, f.w, ss))));
                __nv_bfloat162 h0 = __floats2bfloat162_rn(f.x, f.y);
                __nv_bfloat162 h1 = __floats2bfloat162_rn(f.z, f.w);
                uint32_t off = (uint32_t)(brow * 128 + bhalf * 64 + i * 8);
                asm volatile("st.shared.v2.b32 [%0], {%1, %2};"
                             :: "r"(bufb + A_SZ + SWZ(off)),
                                "r"(*reinterpret_cast<uint32_t*>(&h0)),
                                "r"(*reinterpret_cast<uint32_t*>(&h1)) : "memory");
            }
        }
        if (c < NCHUNK - 1) {   // A cp.async for next chunk into other buffer
            const uint32_t* src = gA + (size_t)tid * 512 + (c + 1) * 32;
            const uint32_t nbuf = sb + (uint32_t)((c + 1) & 1) * BUF;
            #pragma unroll
            for (int u = 0; u < 8; u++) {
                uint32_t dst = nbuf + SWZ((uint32_t)(tid * 128 + u * 16));
                asm volatile("cp.async.ca.shared.global [%0], [%1], 16;"
                             :: "r"(dst), "l"(src + u * 4) : "memory");
            }
            asm volatile("cp.async.commit_group;" ::: "memory");
            asm volatile("cp.async.wait_group 1;" ::: "memory");
        } else {
            asm volatile("cp.async.wait_group 0;" ::: "memory");
        }
        __syncthreads();

        if (c < NCHUNK - 1) {   // prefetch next B into regs (overlaps compute)
            const float* src = gB + (size_t)brow * DIM + (c + 1) * KC + bhalf * 32;
            #pragma unroll
            for (int i = 0; i < 8; i++) pb[i] = *reinterpret_cast<const float4*>(src + i * 4);
        }

        const uint32_t aBase = bufb;
        const uint32_t bBase = bufb + A_SZ;
        const int rsel = lid & 15, usel = lid >> 4;
        #pragma unroll
        for (int ks = 0; ks < 4; ks++) {
            uint32_t afr[4][4], bfr[4][4];
            #pragma unroll
            for (int mt = 0; mt < 4; mt++) {
                int row = wm * 64 + mt * 16 + rsel;
                ldmx4(afr[mt], aBase + SWZ((uint32_t)(row * 128 + (ks * 2 + usel) * 16)));
            }
            #pragma unroll
            for (int np = 0; np < 4; np++) {
                int row = wn * 64 + np * 16 + rsel;
                ldmx4(bfr[np], bBase + SWZ((uint32_t)(row * 128 + (ks * 2 + usel) * 16)));
            }
            #pragma unroll
            for (int mt = 0; mt < 4; mt++)
                #pragma unroll
                for (int np = 0; np < 4; np++) {
                    mma16816(acc[mt][2 * np],     afr[mt], bfr[np][0], bfr[np][2]);
                    mma16816(acc[mt][2 * np + 1], afr[mt], bfr[np][1], bfr[np][3]);
                }
        }
        __syncthreads();
    }

    // gallery inverse norms
    ss += __shfl_xor_sync(~0u, ss, 1);
    if (bhalf == 0)
        reinterpret_cast<float*>(smem + OFF_INVN)[brow] = 1.0f / fmaxf(sqrtf(ss), 1e-8f);
    __syncthreads();
    const float* invn = reinterpret_cast<const float*>(smem + OFF_INVN);

    // epilogue: scale, per-row max, global atomicMax
    #pragma unroll
    for (int mt = 0; mt < 4; mt++) {
        float mx0 = -INFINITY, mx1 = -INFINITY;
        #pragma unroll
        for (int nt = 0; nt < 8; nt++) {
            int colb = wn * 64 + nt * 8 + (lid & 3) * 2;
            float i0 = invn[colb], i1 = invn[colb + 1];
            mx0 = fmaxf(mx0, fmaxf(acc[mt][nt][0] * i0, acc[mt][nt][1] * i1));
            mx1 = fmaxf(mx1, fmaxf(acc[mt][nt][2] * i0, acc[mt][nt][3] * i1));
        }
        #pragma unroll
        for (int o = 1; o <= 2; o <<= 1) {
            mx0 = fmaxf(mx0, __shfl_xor_sync(~0u, mx0, o));
            mx1 = fmaxf(mx1, __shfl_xor_sync(~0u, mx1, o));
        }
        if ((lid & 3) == 0) {
            int r = wm * 64 + mt * 16 + (lid >> 2);
            atomicMax(&g_simmax[l * NQ + r],     enc_f(mx0));
            atomicMax(&g_simmax[l * NQ + r + 8], enc_f(mx1));
        }
    }

    // ---- fused finalize: last CTA reduces + writes output + resets state ----
    __threadfence();                 // make this CTA's atomicMax results visible
    __syncthreads();
    __shared__ unsigned s_last;
    if (tid == 0) s_last = atomicAdd(&g_done, 1u);
    __syncthreads();
    if (s_last == NCTAS - 1) {
        __threadfence();             // acquire: see all other CTAs' maxes
        // thread n computes output for query n
        unsigned v0 = atomicMax(&g_simmax[0 * NQ + tid], 0u);
        unsigned v1 = atomicMax(&g_simmax[1 * NQ + tid], 0u);
        unsigned v2 = atomicMax(&g_simmax[2 * NQ + tid], 0u);
        unsigned v3 = atomicMax(&g_simmax[3 * NQ + tid], 0u);
        float s = dec_f(v0) + dec_f(v1) + dec_f(v2) + dec_f(v3);
        out[tid] = 1.0f - s * (1.0f / NLAYERS);
        __syncthreads();
        // reset for next graph replay (zero == "-inf" under enc)
        #pragma unroll
        for (int l2 = 0; l2 < NLAYERS; l2++) g_simmax[l2 * NQ + tid] = 0u;
        __threadfence();
        __syncthreads();
        if (tid == 0) { g_done = 0u; __threadfence(); }
    }
}

// ---------------- launch ----------------
extern "C" void kernel_launch(void* const* d_in, const int* in_sizes, int n_in,
                              void* d_out, int out_size) {
    const float* q = (const float*)d_in[0];
    const float* g = (const float*)d_in[1];
    if (n_in >= 2 && in_sizes[0] > in_sizes[1]) {
        const float* t = q; q = g; g = t;
    }
    cudaFuncSetAttribute(gemm_max_kernel,
                         cudaFuncAttributeMaxDynamicSharedMemorySize, SMEM_BYTES);

    prep_q_kernel<<<NLAYERS * NQ, 256>>>(q);
    gemm_max_kernel<<<dim3(NTILES, NLAYERS), 256, SMEM_BYTES>>>(g, (float*)d_out);
}

// round 14
// speedup vs baseline: 1.0696x; 1.0696x over previous
#include <cuda_runtime.h>
#include <cuda_fp16.h>
#include <cstdint>
#include <math.h>

#define NLAYERS 4
#define NQ      256
#define DIM     1024
#define MGAL    51200
#define KC      64
#define NCHUNK  (DIM / KC)          // 16
#define TILE_G  128
#define NTILES  (MGAL / TILE_G)     // 400

#define A_SZ    (NQ * 128)          // 32768 B (256 q-rows x 128 B)
#define B_SZ    (TILE_G * 128)      // 16384 B
#define BUF     (A_SZ + B_SZ)       // 49152
#define OFF_INVN (2 * BUF)          // 98304
#define SMEM_BYTES (OFF_INVN + 512)

__device__ uint32_t g_qh[NLAYERS * NQ * DIM / 2];   // f16 queries (normalized), row-major
__device__ unsigned int g_simmax[NLAYERS * NQ];     // monotone-encoded float max

// ---------------- helpers ----------------
__device__ __forceinline__ uint32_t smem_u32(const void* p) {
    uint32_t a;
    asm("{ .reg .u64 t; cvta.to.shared.u64 t, %1; cvt.u32.u64 %0, t; }" : "=r"(a) : "l"(p));
    return a;
}
#define SWZ(o) ((o) ^ (((o) >> 3) & 0x70))

__device__ __forceinline__ unsigned enc_f(float f) {
    unsigned u = __float_as_uint(f);
    return (u & 0x80000000u) ? ~u : (u | 0x80000000u);
}
__device__ __forceinline__ float dec_f(unsigned u) {
    return __uint_as_float((u & 0x80000000u) ? (u & 0x7fffffffu) : ~u);
}
// f16 x f16 -> f16 accumulate, m16n8k16
__device__ __forceinline__ void mma_h(uint32_t* d, const uint32_t* a, uint32_t b0, uint32_t b1) {
    asm volatile(
        "mma.sync.aligned.m16n8k16.row.col.f16.f16.f16.f16 "
        "{%0,%1}, {%2,%3,%4,%5}, {%6,%7}, {%0,%1};"
        : "+r"(d[0]), "+r"(d[1])
        : "r"(a[0]), "r"(a[1]), "r"(a[2]), "r"(a[3]), "r"(b0), "r"(b1));
}
__device__ __forceinline__ void ldmx4(uint32_t* r, uint32_t addr) {
    asm volatile("ldmatrix.sync.aligned.m8n8.x4.shared.b16 {%0,%1,%2,%3}, [%4];"
                 : "=r"(r[0]), "=r"(r[1]), "=r"(r[2]), "=r"(r[3]) : "r"(addr));
}

// ---------------- small kernels ----------------
__global__ void init_kernel() {
    int i = blockIdx.x * blockDim.x + threadIdx.x;
    if (i < NLAYERS * NQ) g_simmax[i] = 0x007FFFFFu;  // enc(-inf)
}

// normalize queries -> f16, row-major
__global__ void prep_q_kernel(const float* __restrict__ q) {
    int row = blockIdx.x;                      // l*NQ + n
    const float4 f = reinterpret_cast<const float4*>(q + (size_t)row * DIM)[threadIdx.x];
    __shared__ float red[8];
    float ss = f.x*f.x + f.y*f.y + f.z*f.z + f.w*f.w;
    #pragma unroll
    for (int o = 16; o; o >>= 1) ss += __shfl_xor_sync(~0u, ss, o);
    if ((threadIdx.x & 31) == 0) red[threadIdx.x >> 5] = ss;
    __syncthreads();
    if (threadIdx.x < 8) {
        float s = red[threadIdx.x];
        #pragma unroll
        for (int o = 4; o; o >>= 1) s += __shfl_xor_sync(0xffu, s, o);
        if (threadIdx.x == 0) red[0] = s;
    }
    __syncthreads();
    float inv = 1.0f / fmaxf(sqrtf(red[0]), 1e-8f);
    __half2 h0 = __floats2half2_rn(f.x * inv, f.y * inv);
    __half2 h1 = __floats2half2_rn(f.z * inv, f.w * inv);
    uint32_t* dst = g_qh + (size_t)row * 512;
    dst[threadIdx.x * 2 + 0] = *reinterpret_cast<uint32_t*>(&h0);
    dst[threadIdx.x * 2 + 1] = *reinterpret_cast<uint32_t*>(&h1);
}

__global__ void finalize_kernel(float* __restrict__ out) {
    int n = threadIdx.x;
    float s = 0.0f;
    #pragma unroll
    for (int l = 0; l < NLAYERS; l++) s += dec_f(g_simmax[l * NQ + n]);
    out[n] = 1.0f - s * (1.0f / NLAYERS);
}

// ---------------- main f16 GEMM + max kernel (round-2 structure, f16 accumulate) ----------------
__global__ __launch_bounds__(256, 1)
void gemm_max_kernel(const float* __restrict__ gal) {
    extern __shared__ char smem[];
    const uint32_t sb = smem_u32(smem);
    const int tid = threadIdx.x, wid = tid >> 5, lid = tid & 31;
    const int l  = blockIdx.y;
    const int g0 = blockIdx.x * TILE_G;
    const float*    gB = gal + ((size_t)l * MGAL + g0) * DIM;
    const uint32_t* gA = g_qh + (size_t)l * NQ * 512;

    const int brow = tid >> 1, bhalf = tid & 1;
    const int wm = wid >> 1, wn = wid & 1;

    // f16x2 accumulators: 64 registers total
    uint32_t acc[4][8][2];
    #pragma unroll
    for (int mt = 0; mt < 4; mt++)
        #pragma unroll
        for (int nt = 0; nt < 8; nt++) { acc[mt][nt][0] = 0u; acc[mt][nt][1] = 0u; }

    float4 pb[8];
    float ss = 0.0f;

    // prologue
    {
        const float* src = gB + (size_t)brow * DIM + bhalf * 32;
        #pragma unroll
        for (int i = 0; i < 8; i++) pb[i] = *reinterpret_cast<const float4*>(src + i * 4);
    }
    {
        const uint32_t* src = gA + (size_t)tid * 512;
        #pragma unroll
        for (int u = 0; u < 8; u++) {
            uint32_t dst = sb + SWZ((uint32_t)(tid * 128 + u * 16));
            asm volatile("cp.async.ca.shared.global [%0], [%1], 16;"
                         :: "r"(dst), "l"(src + u * 4) : "memory");
        }
        asm volatile("cp.async.commit_group;" ::: "memory");
    }

    for (int c = 0; c < NCHUNK; c++) {
        const uint32_t bufb = sb + (uint32_t)(c & 1) * BUF;
        {   // store prefetched B regs -> smem f16 (SW128), accumulate sumsq
            #pragma unroll
            for (int i = 0; i < 8; i++) {
                float4 f = pb[i];
                ss = fmaf(f.x, f.x, fmaf(f.y, f.y, fmaf(f.z, f.z, fmaf(f.w, f.w, ss))));
                __half2 h0 = __floats2half2_rn(f.x, f.y);
                __half2 h1 = __floats2half2_rn(f.z, f.w);
                uint32_t off = (uint32_t)(brow * 128 + bhalf * 64 + i * 8);
                asm volatile("st.shared.v2.b32 [%0], {%1, %2};"
                             :: "r"(bufb + A_SZ + SWZ(off)),
                                "r"(*reinterpret_cast<uint32_t*>(&h0)),
                                "r"(*reinterpret_cast<uint32_t*>(&h1)) : "memory");
            }
        }
        if (c < NCHUNK - 1) {   // A cp.async for next chunk into other buffer
            const uint32_t* src = gA + (size_t)tid * 512 + (c + 1) * 32;
            const uint32_t nbuf = sb + (uint32_t)((c + 1) & 1) * BUF;
            #pragma unroll
            for (int u = 0; u < 8; u++) {
                uint32_t dst = nbuf + SWZ((uint32_t)(tid * 128 + u * 16));
                asm volatile("cp.async.ca.shared.global [%0], [%1], 16;"
                             :: "r"(dst), "l"(src + u * 4) : "memory");
            }
            asm volatile("cp.async.commit_group;" ::: "memory");
            asm volatile("cp.async.wait_group 1;" ::: "memory");
        } else {
            asm volatile("cp.async.wait_group 0;" ::: "memory");
        }
        __syncthreads();

        if (c < NCHUNK - 1) {   // prefetch next B into regs (overlaps compute)
            const float* src = gB + (size_t)brow * DIM + (c + 1) * KC + bhalf * 32;
            #pragma unroll
            for (int i = 0; i < 8; i++) pb[i] = *reinterpret_cast<const float4*>(src + i * 4);
        }

        const uint32_t aBase = bufb;
        const uint32_t bBase = bufb + A_SZ;
        const int rsel = lid & 15, usel = lid >> 4;
        #pragma unroll
        for (int ks = 0; ks < 4; ks++) {
            uint32_t afr[4][4], bfr[4][4];
            #pragma unroll
            for (int mt = 0; mt < 4; mt++) {
                int row = wm * 64 + mt * 16 + rsel;
                ldmx4(afr[mt], aBase + SWZ((uint32_t)(row * 128 + (ks * 2 + usel) * 16)));
            }
            #pragma unroll
            for (int np = 0; np < 4; np++) {
                int row = wn * 64 + np * 16 + rsel;
                ldmx4(bfr[np], bBase + SWZ((uint32_t)(row * 128 + (ks * 2 + usel) * 16)));
            }
            #pragma unroll
            for (int mt = 0; mt < 4; mt++)
                #pragma unroll
                for (int np = 0; np < 4; np++) {
                    mma_h(acc[mt][2 * np],     afr[mt], bfr[np][0], bfr[np][2]);
                    mma_h(acc[mt][2 * np + 1], afr[mt], bfr[np][1], bfr[np][3]);
                }
        }
        __syncthreads();
    }

    // gallery inverse norms
    ss += __shfl_xor_sync(~0u, ss, 1);
    if (bhalf == 0)
        reinterpret_cast<float*>(smem + OFF_INVN)[brow] = 1.0f / fmaxf(sqrtf(ss), 1e-8f);
    __syncthreads();
    const float* invn = reinterpret_cast<const float*>(smem + OFF_INVN);

    // epilogue: unpack f16 acc, scale, per-row max, global atomicMax
    #pragma unroll
    for (int mt = 0; mt < 4; mt++) {
        float mx0 = -INFINITY, mx1 = -INFINITY;   // rows r, r+8
        #pragma unroll
        for (int nt = 0; nt < 8; nt++) {
            int colb = wn * 64 + nt * 8 + (lid & 3) * 2;
            float i0 = invn[colb], i1 = invn[colb + 1];
            __half2 h0 = *reinterpret_cast<__half2*>(&acc[mt][nt][0]);   // cols colb, colb+1 @ row r
            __half2 h1 = *reinterpret_cast<__half2*>(&acc[mt][nt][1]);   // cols colb, colb+1 @ row r+8
            mx0 = fmaxf(mx0, fmaxf(__low2float(h0) * i0, __high2float(h0) * i1));
            mx1 = fmaxf(mx1, fmaxf(__low2float(h1) * i0, __high2float(h1) * i1));
        }
        #pragma unroll
        for (int o = 1; o <= 2; o <<= 1) {
            mx0 = fmaxf(mx0, __shfl_xor_sync(~0u, mx0, o));
            mx1 = fmaxf(mx1, __shfl_xor_sync(~0u, mx1, o));
        }
        if ((lid & 3) == 0) {
            int r = wm * 64 + mt * 16 + (lid >> 2);
            atomicMax(&g_simmax[l * NQ + r],     enc_f(mx0));
            atomicMax(&g_simmax[l * NQ + r + 8], enc_f(mx1));
        }
    }
}

// ---------------- launch ----------------
extern "C" void kernel_launch(void* const* d_in, const int* in_sizes, int n_in,
                              void* d_out, int out_size) {
    const float* q = (const float*)d_in[0];
    const float* g = (const float*)d_in[1];
    if (n_in >= 2 && in_sizes[0] > in_sizes[1]) {
        const float* t = q; q = g; g = t;
    }
    cudaFuncSetAttribute(gemm_max_kernel,
                         cudaFuncAttributeMaxDynamicSharedMemorySize, SMEM_BYTES);

    init_kernel<<<1, NLAYERS * NQ>>>();
    prep_q_kernel<<<NLAYERS * NQ, 256>>>(q);
    gemm_max_kernel<<<dim3(NTILES, NLAYERS), 256, SMEM_BYTES>>>(g);
    finalize_kernel<<<1, NQ>>>((float*)d_out);
}

// round 15
// speedup vs baseline: 1.1392x; 1.0650x over previous
#include <cuda_runtime.h>
#include <cuda_bf16.h>
#include <cstdint>
#include <math.h>

#define NLAYERS 4
#define NQ      256
#define DIM     1024
#define MGAL    51200
#define KC      64
#define NCHUNK  (DIM / KC)          // 16
#define TILE_G  128
#define NTILES  (MGAL / TILE_G)     // 400

#define A_SZ    (NQ * 128)          // 32768 B (256 q-rows x 128 B)
#define B_SZ    (TILE_G * 128)      // 16384 B
#define BUF     (A_SZ + B_SZ)       // 49152
#define OFF_INVN (2 * BUF)          // 98304
#define SMEM_BYTES (OFF_INVN + 512)

__device__ uint32_t g_qbf[NLAYERS * NQ * DIM / 2];  // bf16 queries (normalized), row-major
__device__ unsigned int g_simmax[NLAYERS * NQ];     // monotone-encoded float max

// ---------------- helpers ----------------
__device__ __forceinline__ uint32_t smem_u32(const void* p) {
    uint32_t a;
    asm("{ .reg .u64 t; cvta.to.shared.u64 t, %1; cvt.u32.u64 %0, t; }" : "=r"(a) : "l"(p));
    return a;
}
#define SWZ(o) ((o) ^ (((o) >> 3) & 0x70))

__device__ __forceinline__ unsigned enc_f(float f) {
    unsigned u = __float_as_uint(f);
    return (u & 0x80000000u) ? ~u : (u | 0x80000000u);
}
__device__ __forceinline__ float dec_f(unsigned u) {
    return __uint_as_float((u & 0x80000000u) ? (u & 0x7fffffffu) : ~u);
}
__device__ __forceinline__ void mma16816(float* d, const uint32_t* a, uint32_t b0, uint32_t b1) {
    asm volatile(
        "mma.sync.aligned.m16n8k16.row.col.f32.bf16.bf16.f32 "
        "{%0,%1,%2,%3}, {%4,%5,%6,%7}, {%8,%9}, {%0,%1,%2,%3};"
        : "+f"(d[0]), "+f"(d[1]), "+f"(d[2]), "+f"(d[3])
        : "r"(a[0]), "r"(a[1]), "r"(a[2]), "r"(a[3]), "r"(b0), "r"(b1));
}
__device__ __forceinline__ void ldmx4(uint32_t* r, uint32_t addr) {
    asm volatile("ldmatrix.sync.aligned.m8n8.x4.shared.b16 {%0,%1,%2,%3}, [%4];"
                 : "=r"(r[0]), "=r"(r[1]), "=r"(r[2]), "=r"(r[3]) : "r"(addr));
}

// ---------------- prep: normalize queries -> bf16 (+ init g_simmax) ----------------
__global__ void prep_q_kernel(const float* __restrict__ q) {
    int row = blockIdx.x;                      // l*NQ + n  (0..1023)
    if (threadIdx.x == 0) g_simmax[row] = 0x007FFFFFu;   // enc(-inf)
    const float4 f = reinterpret_cast<const float4*>(q + (size_t)row * DIM)[threadIdx.x];
    __shared__ float red[8];
    float ss = f.x*f.x + f.y*f.y + f.z*f.z + f.w*f.w;
    #pragma unroll
    for (int o = 16; o; o >>= 1) ss += __shfl_xor_sync(~0u, ss, o);
    if ((threadIdx.x & 31) == 0) red[threadIdx.x >> 5] = ss;
    __syncthreads();
    if (threadIdx.x < 8) {
        float s = red[threadIdx.x];
        #pragma unroll
        for (int o = 4; o; o >>= 1) s += __shfl_xor_sync(0xffu, s, o);
        if (threadIdx.x == 0) red[0] = s;
    }
    __syncthreads();
    float inv = 1.0f / fmaxf(sqrtf(red[0]), 1e-8f);
    __nv_bfloat162 h0 = __floats2bfloat162_rn(f.x * inv, f.y * inv);
    __nv_bfloat162 h1 = __floats2bfloat162_rn(f.z * inv, f.w * inv);
    uint32_t* dst = g_qbf + (size_t)row * 512;
    dst[threadIdx.x * 2 + 0] = *reinterpret_cast<uint32_t*>(&h0);
    dst[threadIdx.x * 2 + 1] = *reinterpret_cast<uint32_t*>(&h1);
}

__global__ void finalize_kernel(float* __restrict__ out) {
    int n = threadIdx.x;
    float s = 0.0f;
    #pragma unroll
    for (int l = 0; l < NLAYERS; l++) s += dec_f(g_simmax[l * NQ + n]);
    out[n] = 1.0f - s * (1.0f / NLAYERS);
}

// ---------------- main bf16 GEMM + max kernel (round-2 core, proven 180.4us) ----------------
__global__ __launch_bounds__(256, 1)
void gemm_max_kernel(const float* __restrict__ gal) {
    extern __shared__ char smem[];
    const uint32_t sb = smem_u32(smem);
    const int tid = threadIdx.x, wid = tid >> 5, lid = tid & 31;
    const int l  = blockIdx.y;
    const int g0 = blockIdx.x * TILE_G;
    const float*    gB = gal + ((size_t)l * MGAL + g0) * DIM;
    const uint32_t* gA = g_qbf + (size_t)l * NQ * 512;

    const int brow = tid >> 1, bhalf = tid & 1;
    const int wm = wid >> 1, wn = wid & 1;

    float acc[4][8][4];
    #pragma unroll
    for (int mt = 0; mt < 4; mt++)
        #pragma unroll
        for (int nt = 0; nt < 8; nt++)
            #pragma unroll
            for (int e = 0; e < 4; e++) acc[mt][nt][e] = 0.0f;

    float4 pb[8];
    float ss = 0.0f;

    // prologue
    {
        const float* src = gB + (size_t)brow * DIM + bhalf * 32;
        #pragma unroll
        for (int i = 0; i < 8; i++) pb[i] = *reinterpret_cast<const float4*>(src + i * 4);
    }
    {
        const uint32_t* src = gA + (size_t)tid * 512;
        #pragma unroll
        for (int u = 0; u < 8; u++) {
            uint32_t dst = sb + SWZ((uint32_t)(tid * 128 + u * 16));
            asm volatile("cp.async.ca.shared.global [%0], [%1], 16;"
                         :: "r"(dst), "l"(src + u * 4) : "memory");
        }
        asm volatile("cp.async.commit_group;" ::: "memory");
    }

    for (int c = 0; c < NCHUNK; c++) {
        const uint32_t bufb = sb + (uint32_t)(c & 1) * BUF;
        {   // store prefetched B regs -> smem bf16 (SW128), accumulate sumsq
            #pragma unroll
            for (int i = 0; i < 8; i++) {
                float4 f = pb[i];
                ss = fmaf(f.x, f.x, fmaf(f.y, f.y, fmaf(f.z, f.z, fmaf(f.w, f.w, ss))));
                __nv_bfloat162 h0 = __floats2bfloat162_rn(f.x, f.y);
                __nv_bfloat162 h1 = __floats2bfloat162_rn(f.z, f.w);
                uint32_t off = (uint32_t)(brow * 128 + bhalf * 64 + i * 8);
                asm volatile("st.shared.v2.b32 [%0], {%1, %2};"
                             :: "r"(bufb + A_SZ + SWZ(off)),
                                "r"(*reinterpret_cast<uint32_t*>(&h0)),
                                "r"(*reinterpret_cast<uint32_t*>(&h1)) : "memory");
            }
        }
        if (c < NCHUNK - 1) {   // A cp.async for next chunk into other buffer
            const uint32_t* src = gA + (size_t)tid * 512 + (c + 1) * 32;
            const uint32_t nbuf = sb + (uint32_t)((c + 1) & 1) * BUF;
            #pragma unroll
            for (int u = 0; u < 8; u++) {
                uint32_t dst = nbuf + SWZ((uint32_t)(tid * 128 + u * 16));
                asm volatile("cp.async.ca.shared.global [%0], [%1], 16;"
                             :: "r"(dst), "l"(src + u * 4) : "memory");
            }
            asm volatile("cp.async.commit_group;" ::: "memory");
            asm volatile("cp.async.wait_group 1;" ::: "memory");
        } else {
            asm volatile("cp.async.wait_group 0;" ::: "memory");
        }
        __syncthreads();

        if (c < NCHUNK - 1) {   // prefetch next B into regs (overlaps compute)
            const float* src = gB + (size_t)brow * DIM + (c + 1) * KC + bhalf * 32;
            #pragma unroll
            for (int i = 0; i < 8; i++) pb[i] = *reinterpret_cast<const float4*>(src + i * 4);
        }

        const uint32_t aBase = bufb;
        const uint32_t bBase = bufb + A_SZ;
        const int rsel = lid & 15, usel = lid >> 4;
        #pragma unroll
        for (int ks = 0; ks < 4; ks++) {
            uint32_t afr[4][4], bfr[4][4];
            #pragma unroll
            for (int mt = 0; mt < 4; mt++) {
                int row = wm * 64 + mt * 16 + rsel;
                ldmx4(afr[mt], aBase + SWZ((uint32_t)(row * 128 + (ks * 2 + usel) * 16)));
            }
            #pragma unroll
            for (int np = 0; np < 4; np++) {
                int row = wn * 64 + np * 16 + rsel;
                ldmx4(bfr[np], bBase + SWZ((uint32_t)(row * 128 + (ks * 2 + usel) * 16)));
            }
            #pragma unroll
            for (int mt = 0; mt < 4; mt++)
                #pragma unroll
                for (int np = 0; np < 4; np++) {
                    mma16816(acc[mt][2 * np],     afr[mt], bfr[np][0], bfr[np][2]);
                    mma16816(acc[mt][2 * np + 1], afr[mt], bfr[np][1], bfr[np][3]);
                }
        }
        __syncthreads();
    }

    // gallery inverse norms
    ss += __shfl_xor_sync(~0u, ss, 1);
    if (bhalf == 0)
        reinterpret_cast<float*>(smem + OFF_INVN)[brow] = 1.0f / fmaxf(sqrtf(ss), 1e-8f);
    __syncthreads();
    const float* invn = reinterpret_cast<const float*>(smem + OFF_INVN);

    // epilogue: scale, per-row max, global atomicMax
    #pragma unroll
    for (int mt = 0; mt < 4; mt++) {
        float mx0 = -INFINITY, mx1 = -INFINITY;
        #pragma unroll
        for (int nt = 0; nt < 8; nt++) {
            int colb = wn * 64 + nt * 8 + (lid & 3) * 2;
            float i0 = invn[colb], i1 = invn[colb + 1];
            mx0 = fmaxf(mx0, fmaxf(acc[mt][nt][0] * i0, acc[mt][nt][1] * i1));
            mx1 = fmaxf(mx1, fmaxf(acc[mt][nt][2] * i0, acc[mt][nt][3] * i1));
        }
        #pragma unroll
        for (int o = 1; o <= 2; o <<= 1) {
            mx0 = fmaxf(mx0, __shfl_xor_sync(~0u, mx0, o));
            mx1 = fmaxf(mx1, __shfl_xor_sync(~0u, mx1, o));
        }
        if ((lid & 3) == 0) {
            int r = wm * 64 + mt * 16 + (lid >> 2);
            atomicMax(&g_simmax[l * NQ + r],     enc_f(mx0));
            atomicMax(&g_simmax[l * NQ + r + 8], enc_f(mx1));
        }
    }
}

// ---------------- launch ----------------
extern "C" void kernel_launch(void* const* d_in, const int* in_sizes, int n_in,
                              void* d_out, int out_size) {
    const float* q = (const float*)d_in[0];
    const float* g = (const float*)d_in[1];
    if (n_in >= 2 && in_sizes[0] > in_sizes[1]) {
        const float* t = q; q = g; g = t;
    }
    cudaFuncSetAttribute(gemm_max_kernel,
                         cudaFuncAttributeMaxDynamicSharedMemorySize, SMEM_BYTES);

    prep_q_kernel<<<NLAYERS * NQ, 256>>>(q);
    gemm_max_kernel<<<dim3(NTILES, NLAYERS), 256, SMEM_BYTES>>>(g);
    finalize_kernel<<<1, NQ>>>((float*)d_out);
}

// round 16
// speedup vs baseline: 3.3916x; 2.9773x over previous
#include <cuda_runtime.h>
#include <cuda_bf16.h>
#include <cstdint>
#include <math.h>

#define NLAYERS 4
#define NQ      256
#define DIM     1024
#define MGAL    51200
#define TILE_N  256
#define KC      64
#define NCHUNK  (DIM / KC)        // 16
#define NTHREADS 256
#define NTILES_TOT (MGAL / TILE_N * NLAYERS)   // 800

// ---- tcgen05 persistent kernel SMEM layout ----
#define OFF_TMEM 0
#define OFF_MB0  8
#define OFF_MB1  16
#define OFF_NORM 64                 // 256 floats
#define OFF_A    2048               // A ring: 4 x 32768
#define ARING    32768
#define OFF_B    (OFF_A + 4 * ARING)   // 133120 (1024-aligned)
#define BRING    32768
#define SMEM_BYTES (OFF_B + 2 * BRING) // 198656

// idesc: dtype=F32, atype=btype=BF16, N=256, M=128 (cta_group::1)
#define MMA_IDESC ((1u<<4) | (1u<<7) | (1u<<10) | ((TILE_N/8)<<17) | ((128/16)<<24))

// ---- fallback (mma.sync) config ----
#define FB_TILE_G  128
#define FB_NTILES  (MGAL / FB_TILE_G)   // 400
#define FB_A_SZ    (256 * 128)
#define FB_B_SZ    (128 * 128)
#define FB_BUF     (FB_A_SZ + FB_B_SZ)
#define FB_OFF_INVN (2 * FB_BUF)
#define FB_SMEM    (FB_OFF_INVN + 128 * 4)

__device__ __nv_bfloat16 g_qn[NLAYERS * NQ * DIM];
__device__ unsigned int  g_simmax[NLAYERS * NQ];

// ---------------- helpers ----------------
__device__ __forceinline__ uint32_t smem_u32(const void* p) {
    uint32_t a;
    asm("{ .reg .u64 t; cvta.to.shared.u64 t, %1; cvt.u32.u64 %0, t; }" : "=r"(a) : "l"(p));
    return a;
}
#define SWZ(o) ((o) ^ (((o) >> 3) & 0x70))

__device__ __forceinline__ unsigned enc_f(float f) {
    unsigned u = __float_as_uint(f);
    return (u & 0x80000000u) ? ~u : (u | 0x80000000u);
}
__device__ __forceinline__ float dec_f(unsigned u) {
    return __uint_as_float((u & 0x80000000u) ? (u & 0x7fffffffu) : ~u);
}

// ---------------- common small kernels ----------------
__global__ void init_kernel() {
    int i = blockIdx.x * blockDim.x + threadIdx.x;
    if (i < NLAYERS * NQ) g_simmax[i] = 0x007FFFFFu;  // enc(-inf)
}

__global__ void prep_q_kernel(const float* __restrict__ q) {
    int row = blockIdx.x;                      // l*NQ + n
    const float4 f = reinterpret_cast<const float4*>(q + (size_t)row * DIM)[threadIdx.x];
    __shared__ float red[8];
    float ss = f.x*f.x + f.y*f.y + f.z*f.z + f.w*f.w;
    #pragma unroll
    for (int o = 16; o; o >>= 1) ss += __shfl_xor_sync(~0u, ss, o);
    if ((threadIdx.x & 31) == 0) red[threadIdx.x >> 5] = ss;
    __syncthreads();
    if (threadIdx.x < 8) {
        float s = red[threadIdx.x];
        #pragma unroll
        for (int o = 4; o; o >>= 1) s += __shfl_xor_sync(0xffu, s, o);
        if (threadIdx.x == 0) red[0] = s;
    }
    __syncthreads();
    float inv = 1.0f / fmaxf(sqrtf(red[0]), 1e-8f);
    __nv_bfloat162* dst = reinterpret_cast<__nv_bfloat162*>(g_qn + (size_t)row * DIM);
    dst[threadIdx.x * 2 + 0] = __floats2bfloat162_rn(f.x * inv, f.y * inv);
    dst[threadIdx.x * 2 + 1] = __floats2bfloat162_rn(f.z * inv, f.w * inv);
}

__global__ void finalize_kernel(float* __restrict__ out) {
    int n = threadIdx.x;
    float s = 0.0f;
    #pragma unroll
    for (int l = 0; l < NLAYERS; l++) s += dec_f(g_simmax[l * NQ + n]);
    out[n] = 1.0f - s * (1.0f / NLAYERS);
}

// ===================== tcgen05 path (sm_103a feature-gated) =====================
#if defined(__CUDA_ARCH__)
#if defined(__CUDA_ARCH_FEAT_SM103_ALL)
#define HAS_TCGEN05 1
#endif
#endif

#ifdef HAS_TCGEN05
__device__ __forceinline__ uint64_t make_desc(uint32_t smem_addr) {
    const uint64_t base = (uint64_t(2) << 61) | (uint64_t(1) << 46)
                        | (uint64_t(64) << 32) | (uint64_t(1) << 16);
    return base | ((uint64_t)(smem_addr >> 4) & 0x3FFF);
}
__device__ __forceinline__ void mma_f16_ss(uint32_t d_tmem, uint64_t a_desc,
                                           uint64_t b_desc, uint32_t idesc, uint32_t acc) {
    asm volatile(
        "{\n\t.reg .pred p;\n\t"
        "setp.ne.u32 p, %4, 0;\n\t"
        "tcgen05.mma.cta_group::1.kind::f16 [%0], %1, %2, %3, {%5, %5, %5, %5}, p;\n\t}"
        :: "r"(d_tmem), "l"(a_desc), "l"(b_desc), "r"(idesc), "r"(acc), "r"(0u)
        : "memory");
}
__device__ __forceinline__ void mbar_init(uint32_t addr, uint32_t cnt) {
    asm volatile("mbarrier.init.shared.b64 [%0], %1;" :: "r"(addr), "r"(cnt) : "memory");
}
__device__ __forceinline__ void mbar_wait(uint32_t addr, uint32_t parity) {
    asm volatile(
        "{\n\t.reg .pred P;\n"
        "W_%=:\n\t"
        "mbarrier.try_wait.parity.acquire.cta.shared::cta.b64 P, [%0], %1, 0x989680;\n\t"
        "@!P bra W_%=;\n\t}"
        :: "r"(addr), "r"(parity) : "memory");
}
__device__ __forceinline__ void tc_commit(uint32_t mbar) {
    asm volatile(
        "tcgen05.commit.cta_group::1.mbarrier::arrive::one.shared::cluster.b64 [%0];"
        :: "r"(mbar) : "memory");
}
#define TC_LD_X32(r, tmem_addr) \
    asm volatile( \
        "tcgen05.ld.sync.aligned.32x32b.x32.b32 " \
        "{%0, %1, %2, %3, %4, %5, %6, %7, " \
        " %8, %9, %10, %11, %12, %13, %14, %15, " \
        " %16, %17, %18, %19, %20, %21, %22, %23, " \
        " %24, %25, %26, %27, %28, %29, %30, %31}, [%32];" \
        : "=r"((r)[0]),  "=r"((r)[1]),  "=r"((r)[2]),  "=r"((r)[3]), \
          "=r"((r)[4]),  "=r"((r)[5]),  "=r"((r)[6]),  "=r"((r)[7]), \
          "=r"((r)[8]),  "=r"((r)[9]),  "=r"((r)[10]), "=r"((r)[11]), \
          "=r"((r)[12]), "=r"((r)[13]), "=r"((r)[14]), "=r"((r)[15]), \
          "=r"((r)[16]), "=r"((r)[17]), "=r"((r)[18]), "=r"((r)[19]), \
          "=r"((r)[20]), "=r"((r)[21]), "=r"((r)[22]), "=r"((r)[23]), \
          "=r"((r)[24]), "=r"((r)[25]), "=r"((r)[26]), "=r"((r)[27]), \
          "=r"((r)[28]), "=r"((r)[29]), "=r"((r)[30]), "=r"((r)[31]) \
        : "r"(tmem_addr))

__device__ __forceinline__ const float* b_ptr(const float* gal, int tile, int c) {
    int l = tile & 3, g = tile >> 2;
    return gal + ((size_t)l * MGAL + (size_t)g * TILE_N) * DIM + c * KC;
}
__device__ __forceinline__ const __nv_bfloat16* a_ptr(int tile, int c) {
    int l = tile & 3;
    return g_qn + (size_t)l * NQ * DIM + c * KC;
}
#endif  // HAS_TCGEN05

__global__ __launch_bounds__(NTHREADS, 1)
void gemm_max_kernel(const float* __restrict__ gal) {
#ifdef HAS_TCGEN05
    extern __shared__ char smem[];
    const uint32_t sb = smem_u32(smem);
    const int tid = threadIdx.x;
    const int wid = tid >> 5, lid = tid & 31;
    const int bid = blockIdx.x, G = gridDim.x;

    if (wid == 0) {
        asm volatile("tcgen05.alloc.cta_group::1.sync.aligned.shared::cta.b32 [%0], %1;"
                     :: "r"(sb + OFF_TMEM), "r"(512u) : "memory");
    }
    if (tid == 0) { mbar_init(sb + OFF_MB0, 1); mbar_init(sb + OFF_MB1, 1); }
    __syncthreads();
    uint32_t tmem;
    asm volatile("ld.shared.b32 %0, [%1];" : "=r"(tmem) : "r"(sb + OFF_TMEM));

    const int T  = (NTILES_TOT - bid + G - 1) / G;   // tiles for this CTA
    const int Nc = T * NCHUNK;                       // total chunks

    const int bg = tid >> 4, bc = tid & 15;          // B staging: row group / col4
    const int ag = tid >> 3, au = tid & 7;           // A staging: row group / 16B unit
    float* normArr = reinterpret_cast<float*>(smem + OFF_NORM);

    float4 pbuf[2][16];
    float  ss[16];

    // ---- prologue: prefetch chunk 0 ----
    {
        const float* bp = b_ptr(gal, bid, 0);
        #pragma unroll
        for (int p = 0; p < 16; p++)
            pbuf[0][p] = *reinterpret_cast<const float4*>(bp + (size_t)(p * 16 + bg) * DIM + bc * 4);
        const __nv_bfloat16* ap = a_ptr(bid, 0);
        const uint32_t abase = sb + OFF_A;           // ring slot 0
        #pragma unroll
        for (int p = 0; p < 8; p++) {
            const int row = p * 32 + ag;
            uint32_t dst = abase + ((row >> 7) << 14) + SWZ((uint32_t)((row & 127) * 128 + au * 16));
            asm volatile("cp.async.ca.shared.global [%0], [%1], 16;"
                         :: "r"(dst), "l"(ap + (size_t)row * DIM + au * 8) : "memory");
        }
        asm volatile("cp.async.commit_group;" ::: "memory");
    }

    #pragma unroll 2
    for (int n = 0; n < Nc; n++) {
        const int c = n & 15;
        float4 (&cur)[16] = pbuf[n & 1];
        float4 (&nxt)[16] = pbuf[(n + 1) & 1];

        // ---- prefetch chunk n+1 (B LDG into regs, A cp.async into ring) ----
        if (n + 1 < Nc) {
            const int n1 = n + 1;
            const int tile1 = bid + (n1 >> 4) * G;
            const int c1 = n1 & 15;
            const float* bp = b_ptr(gal, tile1, c1);
            #pragma unroll
            for (int p = 0; p < 16; p++)
                nxt[p] = *reinterpret_cast<const float4*>(bp + (size_t)(p * 16 + bg) * DIM + bc * 4);
            const __nv_bfloat16* ap = a_ptr(tile1, c1);
            const uint32_t abase = sb + OFF_A + (uint32_t)(n1 & 3) * ARING;
            #pragma unroll
            for (int p = 0; p < 8; p++) {
                const int row = p * 32 + ag;
                uint32_t dst = abase + ((row >> 7) << 14) + SWZ((uint32_t)((row & 127) * 128 + au * 16));
                asm volatile("cp.async.ca.shared.global [%0], [%1], 16;"
                             :: "r"(dst), "l"(ap + (size_t)row * DIM + au * 8) : "memory");
            }
            asm volatile("cp.async.commit_group;" ::: "memory");
        }

        // ---- wait: B buffer free (MMA n-2 done) ----
        if (n >= 2) mbar_wait(sb + (((n & 1)) ? OFF_MB1 : OFF_MB0), (unsigned)(((n - 2) >> 1) & 1));

        // ---- wait: A chunk n arrived ----
        if (n + 1 < Nc) asm volatile("cp.async.wait_group 1;" ::: "memory");
        else            asm volatile("cp.async.wait_group 0;" ::: "memory");

        // ---- convert + store B (fp32 -> bf16, SW128), row sumsq ----
        {
            const uint32_t bbase = sb + OFF_B + (uint32_t)(n & 1) * BRING;
            #pragma unroll
            for (int p = 0; p < 16; p++) {
                const int row = p * 16 + bg;
                float4 f = cur[p];
                float s = fmaf(f.x, f.x, fmaf(f.y, f.y, fmaf(f.z, f.z, f.w * f.w)));
                ss[p] = (c == 0) ? s : (ss[p] + s);
                __nv_bfloat162 h0 = __floats2bfloat162_rn(f.x, f.y);
                __nv_bfloat162 h1 = __floats2bfloat162_rn(f.z, f.w);
                uint32_t off = (uint32_t)(row * 128 + bc * 8);
                asm volatile("st.shared.v2.b32 [%0], {%1, %2};"
                             :: "r"(bbase + SWZ(off)),
                                "r"(*reinterpret_cast<uint32_t*>(&h0)),
                                "r"(*reinterpret_cast<uint32_t*>(&h1)) : "memory");
            }
        }

        // ---- at last chunk of tile: reduce sumsq into normArr (raw) ----
        if (c == 15) {
            float sr[16];
            #pragma unroll
            for (int p = 0; p < 16; p++) sr[p] = ss[p];
            #pragma unroll
            for (int o = 1; o < 16; o <<= 1)
                #pragma unroll
                for (int p = 0; p < 16; p++) sr[p] += __shfl_xor_sync(~0u, sr[p], o);
            if (bc == 0) {
                #pragma unroll
                for (int p = 0; p < 16; p++) normArr[p * 16 + bg] = sr[p];
            }
        }

        asm volatile("fence.proxy.async.shared::cta;" ::: "memory");
        __syncthreads();

        // ---- tile boundary: epilogue of previous tile ----
        if (c == 0 && n > 0) {
            normArr[tid] = 1.0f / fmaxf(sqrtf(normArr[tid]), 1e-8f);
            __syncthreads();
            mbar_wait(sb + (((n - 1) & 1) ? OFF_MB1 : OFF_MB0), (unsigned)(((n - 1) >> 1) & 1));
            asm volatile("tcgen05.fence::after_thread_sync;" ::: "memory");

            const int tile_prev = bid + ((n >> 4) - 1) * G;
            const int lprev = tile_prev & 3;
            const uint32_t dbase = tmem + ((wid >= 4) ? TILE_N : 0);
            const int query = ((wid >= 4) ? 128 : 0) + (wid & 3) * 32 + lid;
            float mx = -INFINITY;
            #pragma unroll
            for (int b = 0; b < TILE_N / 32; b++) {
                uint32_t r[32];
                TC_LD_X32(r, dbase + b * 32);
                asm volatile("tcgen05.wait::ld.sync.aligned;" ::: "memory");
                #pragma unroll
                for (int j = 0; j < 32; j++) {
                    float v = __uint_as_float(r[j]) * normArr[b * 32 + j];
                    mx = fmaxf(mx, v);
                }
            }
            atomicMax(&g_simmax[lprev * NQ + query], enc_f(mx));
            asm volatile("tcgen05.fence::before_thread_sync;" ::: "memory");
            __syncthreads();
        }

        // ---- issue MMAs for chunk n ----
        if (tid == 0) {
            const uint32_t abase = sb + OFF_A + (uint32_t)(n & 3) * ARING;
            uint64_t a0 = make_desc(abase);
            uint64_t a1 = make_desc(abase + 16384);
            uint64_t bd = make_desc(sb + OFF_B + (uint32_t)(n & 1) * BRING);
            asm volatile("tcgen05.fence::after_thread_sync;" ::: "memory");
            #pragma unroll
            for (int k = 0; k < KC / 16; k++) {
                uint32_t acc = (c > 0 || k > 0) ? 1u : 0u;
                mma_f16_ss(tmem + 0,      a0 + k * 2, bd + k * 2, MMA_IDESC, acc);
                mma_f16_ss(tmem + TILE_N, a1 + k * 2, bd + k * 2, MMA_IDESC, acc);
            }
            tc_commit(sb + ((n & 1) ? OFF_MB1 : OFF_MB0));
        }
    }

    // ---- final epilogue (last tile) ----
    normArr[tid] = 1.0f / fmaxf(sqrtf(normArr[tid]), 1e-8f);
    __syncthreads();
    mbar_wait(sb + (((Nc - 1) & 1) ? OFF_MB1 : OFF_MB0), (unsigned)(((Nc - 1) >> 1) & 1));
    asm volatile("tcgen05.fence::after_thread_sync;" ::: "memory");
    {
        const int tile_last = bid + (T - 1) * G;
        const int llast = tile_last & 3;
        const uint32_t dbase = tmem + ((wid >= 4) ? TILE_N : 0);
        const int query = ((wid >= 4) ? 128 : 0) + (wid & 3) * 32 + lid;
        float mx = -INFINITY;
        #pragma unroll
        for (int b = 0; b < TILE_N / 32; b++) {
            uint32_t r[32];
            TC_LD_X32(r, dbase + b * 32);
            asm volatile("tcgen05.wait::ld.sync.aligned;" ::: "memory");
            #pragma unroll
            for (int j = 0; j < 32; j++) {
                float v = __uint_as_float(r[j]) * normArr[b * 32 + j];
                mx = fmaxf(mx, v);
            }
        }
        atomicMax(&g_simmax[llast * NQ + query], enc_f(mx));
    }

    __syncthreads();
    if (tid == 0) {
        asm volatile("mbarrier.inval.shared.b64 [%0];" :: "r"(sb + OFF_MB0) : "memory");
        asm volatile("mbarrier.inval.shared.b64 [%0];" :: "r"(sb + OFF_MB1) : "memory");
    }
    if (wid == 0) {
        asm volatile("tcgen05.relinquish_alloc_permit.cta_group::1.sync.aligned;");
        asm volatile("tcgen05.dealloc.cta_group::1.sync.aligned.b32 %0, %1;"
                     :: "r"(tmem), "r"(512u));
    }
#endif  // HAS_TCGEN05
}

// ===================== mma.sync fallback (compiles on any sm_80+) =====================
__device__ __forceinline__ void mma16816(float* d, const uint32_t* a, uint32_t b0, uint32_t b1) {
    asm volatile(
        "mma.sync.aligned.m16n8k16.row.col.f32.bf16.bf16.f32 "
        "{%0,%1,%2,%3}, {%4,%5,%6,%7}, {%8,%9}, {%0,%1,%2,%3};"
        : "+f"(d[0]), "+f"(d[1]), "+f"(d[2]), "+f"(d[3])
        : "r"(a[0]), "r"(a[1]), "r"(a[2]), "r"(a[3]), "r"(b0), "r"(b1));
}
__device__ __forceinline__ void ldmx4(uint32_t* r, uint32_t addr) {
    asm volatile("ldmatrix.sync.aligned.m8n8.x4.shared.b16 {%0,%1,%2,%3}, [%4];"
                 : "=r"(r[0]), "=r"(r[1]), "=r"(r[2]), "=r"(r[3]) : "r"(addr));
}

__global__ __launch_bounds__(256, 1)
void fb_gemm_kernel(const float* __restrict__ gal) {
    extern __shared__ char smem[];
    const uint32_t sb = smem_u32(smem);
    const int tid = threadIdx.x, wid = tid >> 5, lid = tid & 31;
    const int l  = blockIdx.y;
    const int g0 = blockIdx.x * FB_TILE_G;
    const float*         gB = gal + ((size_t)l * MGAL + g0) * DIM;
    const __nv_bfloat16* gA = g_qn + (size_t)l * NQ * DIM;

    const int brow = tid >> 1, bhalf = tid & 1;
    const int wm = wid >> 1, wn = wid & 1;

    float acc[4][8][4];
    #pragma unroll
    for (int mt = 0; mt < 4; mt++)
        #pragma unroll
        for (int nt = 0; nt < 8; nt++)
            #pragma unroll
            for (int e = 0; e < 4; e++) acc[mt][nt][e] = 0.0f;

    float4 pb[8];
    float ss = 0.0f;

    {
        const float* src = gB + (size_t)brow * DIM + bhalf * 32;
        #pragma unroll
        for (int i = 0; i < 8; i++) pb[i] = *reinterpret_cast<const float4*>(src + i * 4);
    }
    {
        const __nv_bfloat16* src = gA + (size_t)tid * DIM;
        #pragma unroll
        for (int u = 0; u < 8; u++) {
            uint32_t dst = sb + SWZ((uint32_t)(tid * 128 + u * 16));
            asm volatile("cp.async.ca.shared.global [%0], [%1], 16;"
                         :: "r"(dst), "l"(src + u * 8) : "memory");
        }
        asm volatile("cp.async.commit_group;" ::: "memory");
    }

    for (int c = 0; c < NCHUNK; c++) {
        const uint32_t bufb = sb + (uint32_t)(c & 1) * FB_BUF;
        {
            #pragma unroll
            for (int i = 0; i < 8; i++) {
                float4 f = pb[i];
                ss = fmaf(f.x, f.x, fmaf(f.y, f.y, fmaf(f.z, f.z, fmaf(f.w, f.w, ss))));
                __nv_bfloat162 h0 = __floats2bfloat162_rn(f.x, f.y);
                __nv_bfloat162 h1 = __floats2bfloat162_rn(f.z, f.w);
                uint32_t off = (uint32_t)(brow * 128 + bhalf * 64 + i * 8);
                asm volatile("st.shared.v2.b32 [%0], {%1, %2};"
                             :: "r"(bufb + FB_A_SZ + SWZ(off)),
                                "r"(*reinterpret_cast<uint32_t*>(&h0)),
                                "r"(*reinterpret_cast<uint32_t*>(&h1)) : "memory");
            }
        }
        if (c < NCHUNK - 1) {
            const __nv_bfloat16* src = gA + (size_t)tid * DIM + (c + 1) * KC;
            const uint32_t nbuf = sb + (uint32_t)((c + 1) & 1) * FB_BUF;
            #pragma unroll
            for (int u = 0; u < 8; u++) {
                uint32_t dst = nbuf + SWZ((uint32_t)(tid * 128 + u * 16));
                asm volatile("cp.async.ca.shared.global [%0], [%1], 16;"
                             :: "r"(dst), "l"(src + u * 8) : "memory");
            }
            asm volatile("cp.async.commit_group;" ::: "memory");
            asm volatile("cp.async.wait_group 1;" ::: "memory");
        } else {
            asm volatile("cp.async.wait_group 0;" ::: "memory");
        }
        __syncthreads();

        if (c < NCHUNK - 1) {
            const float* src = gB + (size_t)brow * DIM + (c + 1) * KC + bhalf * 32;
            #pragma unroll
            for (int i = 0; i < 8; i++) pb[i] = *reinterpret_cast<const float4*>(src + i * 4);
        }

        const uint32_t aBase = bufb;
        const uint32_t bBase = bufb + FB_A_SZ;
        const int rsel = lid & 15, usel = lid >> 4;
        #pragma unroll
        for (int ks = 0; ks < 4; ks++) {
            uint32_t afr[4][4], bfr[4][4];
            #pragma unroll
            for (int mt = 0; mt < 4; mt++) {
                int row = wm * 64 + mt * 16 + rsel;
                ldmx4(afr[mt], aBase + SWZ((uint32_t)(row * 128 + (ks * 2 + usel) * 16)));
            }
            #pragma unroll
            for (int np = 0; np < 4; np++) {
                int row = wn * 64 + np * 16 + rsel;
                ldmx4(bfr[np], bBase + SWZ((uint32_t)(row * 128 + (ks * 2 + usel) * 16)));
            }
            #pragma unroll
            for (int mt = 0; mt < 4; mt++)
                #pragma unroll
                for (int np = 0; np < 4; np++) {
                    mma16816(acc[mt][2 * np],     afr[mt], bfr[np][0], bfr[np][2]);
                    mma16816(acc[mt][2 * np + 1], afr[mt], bfr[np][1], bfr[np][3]);
                }
        }
        __syncthreads();
    }

    ss += __shfl_xor_sync(~0u, ss, 1);
    if (bhalf == 0)
        reinterpret_cast<float*>(smem + FB_OFF_INVN)[brow] = 1.0f / fmaxf(sqrtf(ss), 1e-8f);
    __syncthreads();
    const float* invn = reinterpret_cast<const float*>(smem + FB_OFF_INVN);

    #pragma unroll
    for (int mt = 0; mt < 4; mt++) {
        float mx0 = -INFINITY, mx1 = -INFINITY;
        #pragma unroll
        for (int nt = 0; nt < 8; nt++) {
            int colb = wn * 64 + nt * 8 + (lid & 3) * 2;
            float i0 = invn[colb], i1 = invn[colb + 1];
            mx0 = fmaxf(mx0, fmaxf(acc[mt][nt][0] * i0, acc[mt][nt][1] * i1));
            mx1 = fmaxf(mx1, fmaxf(acc[mt][nt][2] * i0, acc[mt][nt][3] * i1));
        }
        #pragma unroll
        for (int o = 1; o <= 2; o <<= 1) {
            mx0 = fmaxf(mx0, __shfl_xor_sync(~0u, mx0, o));
            mx1 = fmaxf(mx1, __shfl_xor_sync(~0u, mx1, o));
        }
        if ((lid & 3) == 0) {
            int r = wm * 64 + mt * 16 + (lid >> 2);
            atomicMax(&g_simmax[l * NQ + r],     enc_f(mx0));
            atomicMax(&g_simmax[l * NQ + r + 8], enc_f(mx1));
        }
    }
}

// ---------------- launch ----------------
extern "C" void kernel_launch(void* const* d_in, const int* in_sizes, int n_in,
                              void* d_out, int out_size) {
    const float* q = (const float*)d_in[0];
    const float* g = (const float*)d_in[1];
    if (n_in >= 2 && in_sizes[0] > in_sizes[1]) {
        const float* t = q; q = g; g = t;
    }

    int use_tc = 0;
    cudaFuncAttributes attr;
    if (cudaFuncGetAttributes(&attr, gemm_max_kernel) == cudaSuccess && attr.numRegs >= 40)
        use_tc = 1;

    init_kernel<<<1, NLAYERS * NQ>>>();
    prep_q_kernel<<<NLAYERS * NQ, 256>>>(q);
    if (use_tc) {
        int dev = 0, sms = 148;
        cudaGetDevice(&dev);
        cudaDeviceGetAttribute(&sms, cudaDevAttrMultiProcessorCount, dev);
        if (sms < 1) sms = 148;
        if (sms > NTILES_TOT) sms = NTILES_TOT;
        cudaFuncSetAttribute(gemm_max_kernel,
                             cudaFuncAttributeMaxDynamicSharedMemorySize, SMEM_BYTES);
        gemm_max_kernel<<<sms, NTHREADS, SMEM_BYTES>>>(g);
    } else {
        cudaFuncSetAttribute(fb_gemm_kernel,
                             cudaFuncAttributeMaxDynamicSharedMemorySize, FB_SMEM);
        fb_gemm_kernel<<<dim3(FB_NTILES, NLAYERS), 256, FB_SMEM>>>(g);
    }
    finalize_kernel<<<1, NQ>>>((float*)d_out);
}